// round 9
// baseline (speedup 1.0000x reference)
#include <cuda_runtime.h>
#include <cuda_bf16.h>
#include <cstdint>

#define BSZ 1024
#define HD  512
#define DH  256
#define BD  (BSZ*DH)

typedef unsigned long long u64;

// ---------------------------------------------------------------------------
// scratch (__device__ globals; no runtime allocation allowed)
// ---------------------------------------------------------------------------
__device__ float g_qproj[BSZ * HD];                 // q_proj + ba
__device__ float g_part[16 * BD];                   // logit partial slices
__device__ __nv_bfloat16 g_hh_hi[(size_t)BD * HD];  // h_history split high
__device__ __nv_bfloat16 g_hh_lo[(size_t)BD * HD];  // h_history split low
__device__ __nv_bfloat16 g_w_hi[HD * HD];           // Wah split high
__device__ __nv_bfloat16 g_w_lo[HD * HD];           // Wah split low

// ---------------------------------------------------------------------------
// helpers
// ---------------------------------------------------------------------------
__device__ __forceinline__ uint32_t smem_u32(const void* p) {
    uint32_t a;
    asm("{ .reg .u64 t; cvta.to.shared.u64 t, %1; cvt.u32.u64 %0, t; }"
        : "=r"(a) : "l"(p));
    return a;
}
__device__ __forceinline__ void cpa16(uint32_t dst, const void* src) {
    asm volatile("cp.async.cg.shared.global [%0], [%1], 16;" :: "r"(dst), "l"(src));
}
__device__ __forceinline__ void ldsm4(uint32_t* r, uint32_t addr) {
    asm volatile("ldmatrix.sync.aligned.m8n8.x4.shared.b16 {%0,%1,%2,%3}, [%4];"
        : "=r"(r[0]), "=r"(r[1]), "=r"(r[2]), "=r"(r[3]) : "r"(addr));
}
__device__ __forceinline__ void mma16816(float* c, const uint32_t* a, const uint32_t* b) {
    asm volatile(
        "mma.sync.aligned.m16n8k16.row.col.f32.bf16.bf16.f32 "
        "{%0,%1,%2,%3}, {%4,%5,%6,%7}, {%8,%9}, {%0,%1,%2,%3};"
        : "+f"(c[0]), "+f"(c[1]), "+f"(c[2]), "+f"(c[3])
        : "r"(a[0]), "r"(a[1]), "r"(a[2]), "r"(a[3]), "r"(b[0]), "r"(b[1]));
}
__device__ __forceinline__ float fast_tanh(float x) {
    float e = __expf(2.0f * x);
    return 1.0f - 2.0f / (e + 1.0f);
}

// ---------------------------------------------------------------------------
// convert_hh: h_history fp32 -> bf16 hi/lo (one pass; keeps score loop lean)
// ---------------------------------------------------------------------------
__global__ __launch_bounds__(256) void convert_hh_kernel(const float* __restrict__ x) {
    int i = blockIdx.x * blockDim.x + threadIdx.x;
    float4 v = reinterpret_cast<const float4*>(x)[i];
    __nv_bfloat162 h01 = __floats2bfloat162_rn(v.x, v.y);
    __nv_bfloat162 h23 = __floats2bfloat162_rn(v.z, v.w);
    __nv_bfloat162 l01 = __floats2bfloat162_rn(
        v.x - __bfloat162float(h01.x), v.y - __bfloat162float(h01.y));
    __nv_bfloat162 l23 = __floats2bfloat162_rn(
        v.z - __bfloat162float(h23.x), v.w - __bfloat162float(h23.y));
    reinterpret_cast<__nv_bfloat162*>(g_hh_hi)[2 * i]     = h01;
    reinterpret_cast<__nv_bfloat162*>(g_hh_hi)[2 * i + 1] = h23;
    reinterpret_cast<__nv_bfloat162*>(g_hh_lo)[2 * i]     = l01;
    reinterpret_cast<__nv_bfloat162*>(g_hh_lo)[2 * i + 1] = l23;
}

// ---------------------------------------------------------------------------
// convert_w: Wah fp32 -> bf16 hi/lo (1 MB, trivial)
// ---------------------------------------------------------------------------
__global__ __launch_bounds__(256) void convert_w_kernel(const float* __restrict__ x) {
    int i = blockIdx.x * blockDim.x + threadIdx.x;
    float4 v = reinterpret_cast<const float4*>(x)[i];
    __nv_bfloat162 h01 = __floats2bfloat162_rn(v.x, v.y);
    __nv_bfloat162 h23 = __floats2bfloat162_rn(v.z, v.w);
    __nv_bfloat162 l01 = __floats2bfloat162_rn(
        v.x - __bfloat162float(h01.x), v.y - __bfloat162float(h01.y));
    __nv_bfloat162 l23 = __floats2bfloat162_rn(
        v.z - __bfloat162float(h23.x), v.w - __bfloat162float(h23.y));
    reinterpret_cast<__nv_bfloat162*>(g_w_hi)[2 * i]     = h01;
    reinterpret_cast<__nv_bfloat162*>(g_w_hi)[2 * i + 1] = h23;
    reinterpret_cast<__nv_bfloat162*>(g_w_lo)[2 * i]     = l01;
    reinterpret_cast<__nv_bfloat162*>(g_w_lo)[2 * i + 1] = l23;
}

// ---------------------------------------------------------------------------
// qproj: M=1024 N=512 K=1024 fp32; 32x64 tiles -> 256 CTAs
// ---------------------------------------------------------------------------
#define QBK 32
__global__ __launch_bounds__(128) void qproj_kernel(
    const float* __restrict__ h_tilde, const float* __restrict__ c_t,
    const float* __restrict__ Waq, const float* __restrict__ ba)
{
    __shared__ float As[QBK][36];
    __shared__ float Bs[QBK][68];
    const int t  = threadIdx.x;
    const int tx = t & 15, ty = t >> 4;
    const int b0 = blockIdx.x * 32;
    const int g0 = blockIdx.y * 64;

    float acc[4][4] = {};

    for (int k0 = 0; k0 < 2 * HD; k0 += QBK) {
#pragma unroll
        for (int i = 0; i < 8; i++) {
            int idx = t + i * 128;
            int r = idx >> 5, c = idx & 31;
            int j = k0 + c;
            As[c][r] = (j < HD) ? h_tilde[(b0 + r) * HD + j]
                                : c_t[(b0 + r) * HD + (j - HD)];
        }
#pragma unroll
        for (int i = 0; i < 16; i++) {
            int idx = t + i * 128;
            int r = idx >> 5, c = idx & 31;
            Bs[c][r] = Waq[(g0 + r) * (2 * HD) + k0 + c];
        }
        __syncthreads();
#pragma unroll
        for (int k = 0; k < QBK; k++) {
            float4 av = *reinterpret_cast<const float4*>(&As[k][ty * 4]);
            float4 bv = *reinterpret_cast<const float4*>(&Bs[k][tx * 4]);
            float a[4] = {av.x, av.y, av.z, av.w};
            float bb[4] = {bv.x, bv.y, bv.z, bv.w};
#pragma unroll
            for (int i = 0; i < 4; i++)
#pragma unroll
                for (int jj = 0; jj < 4; jj++)
                    acc[i][jj] = fmaf(a[i], bb[jj], acc[i][jj]);
        }
        __syncthreads();
    }

#pragma unroll
    for (int i = 0; i < 4; i++)
#pragma unroll
        for (int jj = 0; jj < 4; jj++)
            g_qproj[(b0 + ty * 4 + i) * HD + (g0 + tx * 4 + jj)] =
                acc[i][jj] + ba[g0 + tx * 4 + jj];
}

// ---------------------------------------------------------------------------
// score: HMMA GEMM, ALL operands pre-split bf16 via cp.async.
// CTA tile 128(M) x 64(N), 8 warps (4M x 2N), warp tile 32x32, 2 CTAs/SM.
// 3-stage, DEPTH-2 prefetch, wait_group 1, ONE __syncthreads per chunk:
//   iter i: wait_group 1 (chunk i landed; i+1 still in flight); sync;
//           cpStage(i+2 -> (i+2)%3) [== (i-1)%3, last read by compute(i-1)];
//           compute(i%3).
// Loads lead consumption by ~2 compute spans -> DRAM latency covered.
// ---------------------------------------------------------------------------
#define SSTR    40                 // smem row stride in halves (80 B)
#define TILE_A  (128 * SSTR)       // halves per A tile (128 x 32)
#define TILE_B  (64 * SSTR)        // halves per B tile (64 x 32)
#define STAGE_H (2*TILE_A + 2*TILE_B)
#define OFF_AL  TILE_A
#define OFF_BH  (2*TILE_A)
#define OFF_BL  (2*TILE_A + TILE_B)
#define NCHUNK  16                 // 512/32
#define NSTAGE  3

__global__ __launch_bounds__(256, 2) void score_mma_kernel(const float* __restrict__ v_t)
{
    extern __shared__ __nv_bfloat16 sm[];
    __shared__ float v_sh[64], qp_sh[64];

    const int t = threadIdx.x;
    const int l = t & 31, wid = t >> 5;
    const int warp_m = wid & 3;       // M offset 32*warp_m
    const int warp_n = wid >> 2;      // N offset 32*warp_n
    const int c2 = (l & 3) * 2;

    const int g0 = blockIdx.x * 64;   // fast dim -> A-tile L2 reuse (8 CTAs)
    const int m0 = blockIdx.y * 128;
    const int b  = m0 / DH;

    const __nv_bfloat16* srcAh = g_hh_hi + (size_t)m0 * HD;
    const __nv_bfloat16* srcAl = g_hh_lo + (size_t)m0 * HD;
    const __nv_bfloat16* srcBh = g_w_hi + (size_t)g0 * HD;
    const __nv_bfloat16* srcBl = g_w_lo + (size_t)g0 * HD;

    const uint32_t smem_base = smem_u32(sm);

    // stage loader: A (hi+lo) 2 tasks/thread/tile, B (hi+lo) 1 task/thread/tile
    auto cpStage = [&](int ch, int st) {
        const uint32_t base = smem_base + (uint32_t)st * STAGE_H * 2;
        const int k0 = ch * 32;
#pragma unroll
        for (int j = 0; j < 2; j++) {
            int task = t + j * 256;               // 0..511
            int row = task >> 2, seg = task & 3;
            uint32_t off = (uint32_t)(row * SSTR) * 2 + (uint32_t)seg * 16;
            size_t so = (size_t)row * HD + k0 + seg * 8;
            cpa16(base + off,              srcAh + so);
            cpa16(base + OFF_AL * 2 + off, srcAl + so);
        }
        {
            int row = t >> 2, seg = t & 3;
            uint32_t off = (uint32_t)(row * SSTR) * 2 + (uint32_t)seg * 16;
            size_t so = (size_t)row * HD + k0 + seg * 8;
            cpa16(base + OFF_BH * 2 + off, srcBh + so);
            cpa16(base + OFF_BL * 2 + off, srcBl + so);
        }
        asm volatile("cp.async.commit_group;" ::: "memory");
    };

    float acc[2][4][4];
#pragma unroll
    for (int mt = 0; mt < 2; mt++)
#pragma unroll
        for (int nt = 0; nt < 4; nt++)
#pragma unroll
            for (int e = 0; e < 4; e++) acc[mt][nt][e] = 0.0f;

    auto compute = [&](int st) {
        const uint32_t sb = smem_base + (uint32_t)st * STAGE_H * 2;
#pragma unroll
        for (int ks = 0; ks < 2; ks++) {
            const int kb = ks * 16;
            uint32_t a_hi[2][4], a_lo[2][4], b_hi[2][4], b_lo[2][4];
#pragma unroll
            for (int mt = 0; mt < 2; mt++) {
                int row = warp_m * 32 + mt * 16 + (l & 7) + ((l >> 3) & 1) * 8;
                int col = kb + ((l >> 4) & 1) * 8;
                uint32_t off = (uint32_t)(row * SSTR + col) * 2;
                ldsm4(a_hi[mt], sb + off);
                ldsm4(a_lo[mt], sb + OFF_AL * 2 + off);
            }
#pragma unroll
            for (int p = 0; p < 2; p++) {
                int n = warp_n * 32 + p * 16 + (l & 7) + ((l >> 4) & 1) * 8;
                int col = kb + ((l >> 3) & 1) * 8;
                uint32_t off = (uint32_t)(n * SSTR + col) * 2;
                ldsm4(b_hi[p], sb + OFF_BH * 2 + off);
                ldsm4(b_lo[p], sb + OFF_BL * 2 + off);
            }
            // 3 split products, acc reuse distance = 8 MMAs
#pragma unroll
            for (int p = 0; p < 2; p++)
#pragma unroll
                for (int h = 0; h < 2; h++)
#pragma unroll
                    for (int mt = 0; mt < 2; mt++)
                        mma16816(acc[mt][2 * p + h], a_hi[mt], &b_hi[p][2 * h]);
#pragma unroll
            for (int p = 0; p < 2; p++)
#pragma unroll
                for (int h = 0; h < 2; h++)
#pragma unroll
                    for (int mt = 0; mt < 2; mt++)
                        mma16816(acc[mt][2 * p + h], a_hi[mt], &b_lo[p][2 * h]);
#pragma unroll
            for (int p = 0; p < 2; p++)
#pragma unroll
                for (int h = 0; h < 2; h++)
#pragma unroll
                    for (int mt = 0; mt < 2; mt++)
                        mma16816(acc[mt][2 * p + h], a_lo[mt], &b_hi[p][2 * h]);
        }
    };

    cpStage(0, 0);                      // depth-2 prefetch
    cpStage(1, 1);

    if (t < 64) {
        v_sh[t]  = v_t[g0 + t];
        qp_sh[t] = g_qproj[b * HD + g0 + t];
    }

#pragma unroll 1
    for (int i = 0; i < NCHUNK; i++) {
        const int s = i % NSTAGE;
        if (i + 1 < NCHUNK) {
            asm volatile("cp.async.wait_group 1;" ::: "memory");  // chunk i done
        } else {
            asm volatile("cp.async.wait_group 0;" ::: "memory");
        }
        __syncthreads();                  // everyone finished compute(i-1)
        if (i + 2 < NCHUNK)
            cpStage(i + 2, (i + 2) % NSTAGE);  // stage last read by compute(i-1)
        compute(s);
    }

    // epilogue: tanh + v-dot, quad reduce, store into partial slice
    const int slice = blockIdx.x * 2 + warp_n;     // 0..15
    const int q = l >> 2;
#pragma unroll
    for (int mt = 0; mt < 2; mt++) {
        float rs0 = 0.0f, rs1 = 0.0f;
#pragma unroll
        for (int nt = 0; nt < 4; nt++) {
            const int gbase = warp_n * 32 + nt * 8 + c2;
            const float vq0 = v_sh[gbase],     qq0 = qp_sh[gbase];
            const float vq1 = v_sh[gbase + 1], qq1 = qp_sh[gbase + 1];
            rs0 += vq0 * fast_tanh(acc[mt][nt][0] + qq0);
            rs0 += vq1 * fast_tanh(acc[mt][nt][1] + qq1);
            rs1 += vq0 * fast_tanh(acc[mt][nt][2] + qq0);
            rs1 += vq1 * fast_tanh(acc[mt][nt][3] + qq1);
        }
        rs0 += __shfl_xor_sync(0xffffffffu, rs0, 1);
        rs0 += __shfl_xor_sync(0xffffffffu, rs0, 2);
        rs1 += __shfl_xor_sync(0xffffffffu, rs1, 1);
        rs1 += __shfl_xor_sync(0xffffffffu, rs1, 2);
        if ((l & 3) == 0) {
            const int rowb = m0 + warp_m * 32 + mt * 16 + q;
            g_part[(size_t)slice * BD + rowb]     = rs0;
            g_part[(size_t)slice * BD + rowb + 8] = rs1;
        }
    }
}

// ---------------------------------------------------------------------------
// softmax: sum 16 partial slices, then softmax over d
// ---------------------------------------------------------------------------
__global__ __launch_bounds__(DH) void softmax_kernel(float* __restrict__ alpha_out)
{
    __shared__ float red[DH];
    const int b = blockIdx.x, d = threadIdx.x;
    const int row = b * DH + d;
    float x = 0.0f;
#pragma unroll
    for (int s = 0; s < 16; s++) x += g_part[(size_t)s * BD + row];
    red[d] = x;
    __syncthreads();
    for (int s = DH / 2; s > 0; s >>= 1) {
        if (d < s) red[d] = fmaxf(red[d], red[d + s]);
        __syncthreads();
    }
    float mx = red[0];
    __syncthreads();
    float e = __expf(x - mx);
    red[d] = e;
    __syncthreads();
    for (int s = DH / 2; s > 0; s >>= 1) {
        if (d < s) red[d] += red[d + s];
        __syncthreads();
    }
    alpha_out[row] = e / red[0];
}

// ---------------------------------------------------------------------------
// e_t = alpha . h_history  — 128 thr x float4, full-row coalesced
// ---------------------------------------------------------------------------
__global__ __launch_bounds__(128) void et_kernel(
    const float* __restrict__ hh, const float* __restrict__ alpha,
    float* __restrict__ e_out)
{
    __shared__ float al[DH];
    const int b = blockIdx.x, t = threadIdx.x;
    al[t]       = alpha[b * DH + t];
    al[t + 128] = alpha[b * DH + t + 128];
    __syncthreads();
    const float4* basep = reinterpret_cast<const float4*>(
        hh + (size_t)b * DH * HD) + t;
    float ax = 0.f, ay = 0.f, az = 0.f, aw = 0.f;
#pragma unroll 4
    for (int d = 0; d < DH; d++) {
        float4 v = basep[(size_t)d * (HD / 4)];
        float a = al[d];
        ax = fmaf(a, v.x, ax);
        ay = fmaf(a, v.y, ay);
        az = fmaf(a, v.z, az);
        aw = fmaf(a, v.w, aw);
    }
    reinterpret_cast<float4*>(e_out + b * HD)[t] = make_float4(ax, ay, az, aw);
}

// ---------------------------------------------------------------------------
// launch
// inputs: 0 h_tilde | 1 c_t | 2 h_history | 3 Waq | 4 Wah | 5 ba | 6 v_t
// out = [e_t (B*H) | alpha (B*D)]
// ---------------------------------------------------------------------------
extern "C" void kernel_launch(void* const* d_in, const int* in_sizes, int n_in,
                              void* d_out, int out_size)
{
    const float* h_tilde = (const float*)d_in[0];
    const float* c_t     = (const float*)d_in[1];
    const float* hh      = (const float*)d_in[2];
    const float* Waq     = (const float*)d_in[3];
    const float* Wah     = (const float*)d_in[4];
    const float* ba      = (const float*)d_in[5];
    const float* v_t     = (const float*)d_in[6];

    float* out       = (float*)d_out;
    float* e_out     = out;               // [B, H]
    float* alpha_out = out + BSZ * HD;    // [B, D]

    cudaFuncSetAttribute(score_mma_kernel,
                         cudaFuncAttributeMaxDynamicSharedMemorySize,
                         NSTAGE * STAGE_H * 2);

    convert_w_kernel<<<(HD * HD / 4) / 256, 256>>>(Wah);            // 1
    convert_hh_kernel<<<((size_t)BD * HD / 4) / 256, 256>>>(hh);    // 2

    dim3 g1(BSZ / 32, HD / 64);
    qproj_kernel<<<g1, 128>>>(h_tilde, c_t, Waq, ba);               // 3

    dim3 g2(HD / 64, BD / 128);    // g0 fastest -> A-tile L2 reuse (8 CTAs)
    score_mma_kernel<<<g2, 256, NSTAGE * STAGE_H * 2>>>(v_t);       // 4 (profiled)

    softmax_kernel<<<BSZ, DH>>>(alpha_out);                         // 5

    et_kernel<<<BSZ, 128>>>(hh, alpha_out, e_out);                  // 6
}

// round 11
// speedup vs baseline: 1.1218x; 1.1218x over previous
#include <cuda_runtime.h>
#include <cuda_bf16.h>
#include <cstdint>

#define BSZ 1024
#define HD  512
#define DH  256
#define BD  (BSZ*DH)

typedef unsigned long long u64;

// ---------------------------------------------------------------------------
// scratch (__device__ globals; no runtime allocation allowed)
// ---------------------------------------------------------------------------
__device__ float g_qproj[BSZ * HD];                 // q_proj + ba
__device__ float g_part[8 * BD];                    // logit partial slices
__device__ __nv_bfloat16 g_hh_hi[(size_t)BD * HD];  // h_history split high
__device__ __nv_bfloat16 g_hh_lo[(size_t)BD * HD];  // h_history split low
__device__ __nv_bfloat16 g_w_hi[HD * HD];           // Wah split high
__device__ __nv_bfloat16 g_w_lo[HD * HD];           // Wah split low

// ---------------------------------------------------------------------------
// helpers
// ---------------------------------------------------------------------------
__device__ __forceinline__ uint32_t smem_u32(const void* p) {
    uint32_t a;
    asm("{ .reg .u64 t; cvta.to.shared.u64 t, %1; cvt.u32.u64 %0, t; }"
        : "=r"(a) : "l"(p));
    return a;
}
__device__ __forceinline__ void cpa16(uint32_t dst, const void* src) {
    asm volatile("cp.async.cg.shared.global [%0], [%1], 16;" :: "r"(dst), "l"(src));
}
__device__ __forceinline__ void ldsm4(uint32_t* r, uint32_t addr) {
    asm volatile("ldmatrix.sync.aligned.m8n8.x4.shared.b16 {%0,%1,%2,%3}, [%4];"
        : "=r"(r[0]), "=r"(r[1]), "=r"(r[2]), "=r"(r[3]) : "r"(addr));
}
__device__ __forceinline__ void mma16816(float* c, const uint32_t* a, const uint32_t* b) {
    asm volatile(
        "mma.sync.aligned.m16n8k16.row.col.f32.bf16.bf16.f32 "
        "{%0,%1,%2,%3}, {%4,%5,%6,%7}, {%8,%9}, {%0,%1,%2,%3};"
        : "+f"(c[0]), "+f"(c[1]), "+f"(c[2]), "+f"(c[3])
        : "r"(a[0]), "r"(a[1]), "r"(a[2]), "r"(a[3]), "r"(b[0]), "r"(b[1]));
}
__device__ __forceinline__ float fast_tanh(float x) {
    float e = __expf(2.0f * x);
    return 1.0f - 2.0f / (e + 1.0f);
}

// ---------------------------------------------------------------------------
// convert_hh: h_history fp32 -> bf16 hi/lo (one pass; keeps score loop lean)
// ---------------------------------------------------------------------------
__global__ __launch_bounds__(256) void convert_hh_kernel(const float* __restrict__ x) {
    int i = blockIdx.x * blockDim.x + threadIdx.x;
    float4 v = reinterpret_cast<const float4*>(x)[i];
    __nv_bfloat162 h01 = __floats2bfloat162_rn(v.x, v.y);
    __nv_bfloat162 h23 = __floats2bfloat162_rn(v.z, v.w);
    __nv_bfloat162 l01 = __floats2bfloat162_rn(
        v.x - __bfloat162float(h01.x), v.y - __bfloat162float(h01.y));
    __nv_bfloat162 l23 = __floats2bfloat162_rn(
        v.z - __bfloat162float(h23.x), v.w - __bfloat162float(h23.y));
    reinterpret_cast<__nv_bfloat162*>(g_hh_hi)[2 * i]     = h01;
    reinterpret_cast<__nv_bfloat162*>(g_hh_hi)[2 * i + 1] = h23;
    reinterpret_cast<__nv_bfloat162*>(g_hh_lo)[2 * i]     = l01;
    reinterpret_cast<__nv_bfloat162*>(g_hh_lo)[2 * i + 1] = l23;
}

// ---------------------------------------------------------------------------
// convert_w: Wah fp32 -> bf16 hi/lo (1 MB, trivial)
// ---------------------------------------------------------------------------
__global__ __launch_bounds__(256) void convert_w_kernel(const float* __restrict__ x) {
    int i = blockIdx.x * blockDim.x + threadIdx.x;
    float4 v = reinterpret_cast<const float4*>(x)[i];
    __nv_bfloat162 h01 = __floats2bfloat162_rn(v.x, v.y);
    __nv_bfloat162 h23 = __floats2bfloat162_rn(v.z, v.w);
    __nv_bfloat162 l01 = __floats2bfloat162_rn(
        v.x - __bfloat162float(h01.x), v.y - __bfloat162float(h01.y));
    __nv_bfloat162 l23 = __floats2bfloat162_rn(
        v.z - __bfloat162float(h23.x), v.w - __bfloat162float(h23.y));
    reinterpret_cast<__nv_bfloat162*>(g_w_hi)[2 * i]     = h01;
    reinterpret_cast<__nv_bfloat162*>(g_w_hi)[2 * i + 1] = h23;
    reinterpret_cast<__nv_bfloat162*>(g_w_lo)[2 * i]     = l01;
    reinterpret_cast<__nv_bfloat162*>(g_w_lo)[2 * i + 1] = l23;
}

// ---------------------------------------------------------------------------
// qproj: M=1024 N=512 K=1024 fp32; 32x64 tiles -> 256 CTAs
// ---------------------------------------------------------------------------
#define QBK 32
__global__ __launch_bounds__(128) void qproj_kernel(
    const float* __restrict__ h_tilde, const float* __restrict__ c_t,
    const float* __restrict__ Waq, const float* __restrict__ ba)
{
    __shared__ float As[QBK][36];
    __shared__ float Bs[QBK][68];
    const int t  = threadIdx.x;
    const int tx = t & 15, ty = t >> 4;
    const int b0 = blockIdx.x * 32;
    const int g0 = blockIdx.y * 64;

    float acc[4][4] = {};

    for (int k0 = 0; k0 < 2 * HD; k0 += QBK) {
#pragma unroll
        for (int i = 0; i < 8; i++) {
            int idx = t + i * 128;
            int r = idx >> 5, c = idx & 31;
            int j = k0 + c;
            As[c][r] = (j < HD) ? h_tilde[(b0 + r) * HD + j]
                                : c_t[(b0 + r) * HD + (j - HD)];
        }
#pragma unroll
        for (int i = 0; i < 16; i++) {
            int idx = t + i * 128;
            int r = idx >> 5, c = idx & 31;
            Bs[c][r] = Waq[(g0 + r) * (2 * HD) + k0 + c];
        }
        __syncthreads();
#pragma unroll
        for (int k = 0; k < QBK; k++) {
            float4 av = *reinterpret_cast<const float4*>(&As[k][ty * 4]);
            float4 bv = *reinterpret_cast<const float4*>(&Bs[k][tx * 4]);
            float a[4] = {av.x, av.y, av.z, av.w};
            float bb[4] = {bv.x, bv.y, bv.z, bv.w};
#pragma unroll
            for (int i = 0; i < 4; i++)
#pragma unroll
                for (int jj = 0; jj < 4; jj++)
                    acc[i][jj] = fmaf(a[i], bb[jj], acc[i][jj]);
        }
        __syncthreads();
    }

#pragma unroll
    for (int i = 0; i < 4; i++)
#pragma unroll
        for (int jj = 0; jj < 4; jj++)
            g_qproj[(b0 + ty * 4 + i) * HD + (g0 + tx * 4 + jj)] =
                acc[i][jj] + ba[g0 + tx * 4 + jj];
}

// ---------------------------------------------------------------------------
// score: HMMA GEMM, pre-split bf16 operands via cp.async.
// CTA tile 128(M) x 128(N), 8 warps (4M x 2N), warp tile 32x64, 2 CTAs/SM.
// Fat warp tile cuts smem traffic: ~171 B/MMA vs 250 at 32x32.
// Loader (FIXED vs R10): each 128x32-half tile = 512 x 16B segs
//   -> task = t + j*256 (j<2), row = task>>2, seg = task&3;
//   each task issues one cpa16 per tile (Ah, Al, Bh, Bl) = 8/thread total.
// 2-stage; cp for chunk i+1 issued BEFORE wait_group so loads lead by a full
// compute span; two barriers/chunk (trailing one protects stage reuse).
// ---------------------------------------------------------------------------
#define SSTR    40                 // smem row stride in halves (80 B)
#define TILE_H  (128 * SSTR)       // halves per 128x32 tile
#define STAGE_H (4 * TILE_H)       // Ah, Al, Bh, Bl
#define OFF_AL  TILE_H
#define OFF_BH  (2 * TILE_H)
#define OFF_BL  (3 * TILE_H)
#define NCHUNK  16                 // 512/32

__global__ __launch_bounds__(256, 2) void score_mma_kernel(const float* __restrict__ v_t)
{
    extern __shared__ __nv_bfloat16 sm[];
    __shared__ float v_sh[128], qp_sh[128];

    const int t = threadIdx.x;
    const int l = t & 31, wid = t >> 5;
    const int warp_m = wid & 3;       // M offset 32*warp_m
    const int warp_n = wid >> 2;      // N offset 64*warp_n
    const int c2 = (l & 3) * 2;

    const int g0 = blockIdx.x * 128;  // fast dim -> A-tile L2 reuse (4 CTAs)
    const int m0 = blockIdx.y * 128;
    const int b  = m0 / DH;

    const __nv_bfloat16* srcAh = g_hh_hi + (size_t)m0 * HD;
    const __nv_bfloat16* srcAl = g_hh_lo + (size_t)m0 * HD;
    const __nv_bfloat16* srcBh = g_w_hi + (size_t)g0 * HD;
    const __nv_bfloat16* srcBl = g_w_lo + (size_t)g0 * HD;

    const uint32_t smem_base = smem_u32(sm);

    // stage loader: 4 tiles (Ah,Al,Bh,Bl), each 128 rows x 32 halves.
    // 512 segs/tile; 2 tasks/thread; 4 cpa16 per task (one per tile).
    auto cpStage = [&](int ch, int st) {
        const uint32_t base = smem_base + (uint32_t)st * STAGE_H * 2;
        const int k0 = ch * 32;
#pragma unroll
        for (int j = 0; j < 2; j++) {
            int task = t + j * 256;               // 0..511
            int row = task >> 2, seg = task & 3;  // row 0..127, seg 0..3
            uint32_t off = (uint32_t)(row * SSTR) * 2 + (uint32_t)seg * 16;
            size_t so = (size_t)row * HD + k0 + seg * 8;
            cpa16(base + off,              srcAh + so);
            cpa16(base + OFF_AL * 2 + off, srcAl + so);
            cpa16(base + OFF_BH * 2 + off, srcBh + so);
            cpa16(base + OFF_BL * 2 + off, srcBl + so);
        }
        asm volatile("cp.async.commit_group;" ::: "memory");
    };

    float acc[2][8][4];
#pragma unroll
    for (int mt = 0; mt < 2; mt++)
#pragma unroll
        for (int nt = 0; nt < 8; nt++)
#pragma unroll
            for (int e = 0; e < 4; e++) acc[mt][nt][e] = 0.0f;

    auto compute = [&](int st) {
        const uint32_t sb = smem_base + (uint32_t)st * STAGE_H * 2;
#pragma unroll
        for (int ks = 0; ks < 2; ks++) {
            const int kb = ks * 16;
            uint32_t a_hi[2][4], a_lo[2][4], b_hi[4][4], b_lo[4][4];
#pragma unroll
            for (int mt = 0; mt < 2; mt++) {
                int row = warp_m * 32 + mt * 16 + (l & 7) + ((l >> 3) & 1) * 8;
                int col = kb + ((l >> 4) & 1) * 8;
                uint32_t off = (uint32_t)(row * SSTR + col) * 2;
                ldsm4(a_hi[mt], sb + off);
                ldsm4(a_lo[mt], sb + OFF_AL * 2 + off);
            }
#pragma unroll
            for (int p = 0; p < 4; p++) {
                int n = warp_n * 64 + p * 16 + (l & 7) + ((l >> 4) & 1) * 8;
                int col = kb + ((l >> 3) & 1) * 8;
                uint32_t off = (uint32_t)(n * SSTR + col) * 2;
                ldsm4(b_hi[p], sb + OFF_BH * 2 + off);
                ldsm4(b_lo[p], sb + OFF_BL * 2 + off);
            }
            // 3 split products; acc reuse distance = 16 MMAs
#pragma unroll
            for (int p = 0; p < 4; p++)
#pragma unroll
                for (int h = 0; h < 2; h++)
#pragma unroll
                    for (int mt = 0; mt < 2; mt++)
                        mma16816(acc[mt][2 * p + h], a_hi[mt], &b_hi[p][2 * h]);
#pragma unroll
            for (int p = 0; p < 4; p++)
#pragma unroll
                for (int h = 0; h < 2; h++)
#pragma unroll
                    for (int mt = 0; mt < 2; mt++)
                        mma16816(acc[mt][2 * p + h], a_hi[mt], &b_lo[p][2 * h]);
#pragma unroll
            for (int p = 0; p < 4; p++)
#pragma unroll
                for (int h = 0; h < 2; h++)
#pragma unroll
                    for (int mt = 0; mt < 2; mt++)
                        mma16816(acc[mt][2 * p + h], a_lo[mt], &b_hi[p][2 * h]);
        }
    };

    cpStage(0, 0);

    if (t < 128) {
        v_sh[t]  = v_t[g0 + t];
        qp_sh[t] = g_qproj[b * HD + g0 + t];
    }

#pragma unroll 1
    for (int i = 0; i < NCHUNK; i++) {
        const int s = i & 1;
        if (i + 1 < NCHUNK) {
            cpStage(i + 1, s ^ 1);   // issue early: loads lead by one compute
            asm volatile("cp.async.wait_group 1;" ::: "memory"); // chunk i done
        } else {
            asm volatile("cp.async.wait_group 0;" ::: "memory");
        }
        __syncthreads();             // stage s data visible to all warps
        compute(s);
        __syncthreads();             // protect stage s from next cp overwrite
    }

    // epilogue: tanh + v-dot, quad reduce, store into partial slice
    const int slice = blockIdx.x * 2 + warp_n;     // 0..7
    const int q = l >> 2;
#pragma unroll
    for (int mt = 0; mt < 2; mt++) {
        float rs0 = 0.0f, rs1 = 0.0f;
#pragma unroll
        for (int nt = 0; nt < 8; nt++) {
            const int gbase = warp_n * 64 + nt * 8 + c2;
            const float vq0 = v_sh[gbase],     qq0 = qp_sh[gbase];
            const float vq1 = v_sh[gbase + 1], qq1 = qp_sh[gbase + 1];
            rs0 += vq0 * fast_tanh(acc[mt][nt][0] + qq0);
            rs0 += vq1 * fast_tanh(acc[mt][nt][1] + qq1);
            rs1 += vq0 * fast_tanh(acc[mt][nt][2] + qq0);
            rs1 += vq1 * fast_tanh(acc[mt][nt][3] + qq1);
        }
        rs0 += __shfl_xor_sync(0xffffffffu, rs0, 1);
        rs0 += __shfl_xor_sync(0xffffffffu, rs0, 2);
        rs1 += __shfl_xor_sync(0xffffffffu, rs1, 1);
        rs1 += __shfl_xor_sync(0xffffffffu, rs1, 2);
        if ((l & 3) == 0) {
            const int rowb = m0 + warp_m * 32 + mt * 16 + q;
            g_part[(size_t)slice * BD + rowb]     = rs0;
            g_part[(size_t)slice * BD + rowb + 8] = rs1;
        }
    }
}

// ---------------------------------------------------------------------------
// softmax: sum 8 partial slices, then softmax over d
// ---------------------------------------------------------------------------
__global__ __launch_bounds__(DH) void softmax_kernel(float* __restrict__ alpha_out)
{
    __shared__ float red[DH];
    const int b = blockIdx.x, d = threadIdx.x;
    const int row = b * DH + d;
    float x = 0.0f;
#pragma unroll
    for (int s = 0; s < 8; s++) x += g_part[(size_t)s * BD + row];
    red[d] = x;
    __syncthreads();
    for (int s = DH / 2; s > 0; s >>= 1) {
        if (d < s) red[d] = fmaxf(red[d], red[d + s]);
        __syncthreads();
    }
    float mx = red[0];
    __syncthreads();
    float e = __expf(x - mx);
    red[d] = e;
    __syncthreads();
    for (int s = DH / 2; s > 0; s >>= 1) {
        if (d < s) red[d] += red[d + s];
        __syncthreads();
    }
    alpha_out[row] = e / red[0];
}

// ---------------------------------------------------------------------------
// e_t = alpha . h_history  — 128 thr x float4, full-row coalesced
// ---------------------------------------------------------------------------
__global__ __launch_bounds__(128) void et_kernel(
    const float* __restrict__ hh, const float* __restrict__ alpha,
    float* __restrict__ e_out)
{
    __shared__ float al[DH];
    const int b = blockIdx.x, t = threadIdx.x;
    al[t]       = alpha[b * DH + t];
    al[t + 128] = alpha[b * DH + t + 128];
    __syncthreads();
    const float4* basep = reinterpret_cast<const float4*>(
        hh + (size_t)b * DH * HD) + t;
    float ax = 0.f, ay = 0.f, az = 0.f, aw = 0.f;
#pragma unroll 4
    for (int d = 0; d < DH; d++) {
        float4 v = basep[(size_t)d * (HD / 4)];
        float a = al[d];
        ax = fmaf(a, v.x, ax);
        ay = fmaf(a, v.y, ay);
        az = fmaf(a, v.z, az);
        aw = fmaf(a, v.w, aw);
    }
    reinterpret_cast<float4*>(e_out + b * HD)[t] = make_float4(ax, ay, az, aw);
}

// ---------------------------------------------------------------------------
// launch
// inputs: 0 h_tilde | 1 c_t | 2 h_history | 3 Waq | 4 Wah | 5 ba | 6 v_t
// out = [e_t (B*H) | alpha (B*D)]
// ---------------------------------------------------------------------------
extern "C" void kernel_launch(void* const* d_in, const int* in_sizes, int n_in,
                              void* d_out, int out_size)
{
    const float* h_tilde = (const float*)d_in[0];
    const float* c_t     = (const float*)d_in[1];
    const float* hh      = (const float*)d_in[2];
    const float* Waq     = (const float*)d_in[3];
    const float* Wah     = (const float*)d_in[4];
    const float* ba      = (const float*)d_in[5];
    const float* v_t     = (const float*)d_in[6];

    float* out       = (float*)d_out;
    float* e_out     = out;               // [B, H]
    float* alpha_out = out + BSZ * HD;    // [B, D]

    cudaFuncSetAttribute(score_mma_kernel,
                         cudaFuncAttributeMaxDynamicSharedMemorySize,
                         2 * STAGE_H * 2);

    convert_w_kernel<<<(HD * HD / 4) / 256, 256>>>(Wah);            // 1
    convert_hh_kernel<<<((size_t)BD * HD / 4) / 256, 256>>>(hh);    // 2

    dim3 g1(BSZ / 32, HD / 64);
    qproj_kernel<<<g1, 128>>>(h_tilde, c_t, Waq, ba);               // 3

    dim3 g2(HD / 128, BD / 128);   // g0 fastest -> A-tile L2 reuse (4 CTAs)
    score_mma_kernel<<<g2, 256, 2 * STAGE_H * 2>>>(v_t);            // 4 (profiled)

    softmax_kernel<<<BSZ, DH>>>(alpha_out);                         // 5

    et_kernel<<<BSZ, 128>>>(hh, alpha_out, e_out);                  // 6
}

// round 12
// speedup vs baseline: 1.1249x; 1.0028x over previous
#include <cuda_runtime.h>
#include <cuda_bf16.h>
#include <cstdint>

#define BSZ 1024
#define HD  512
#define DH  256
#define BD  (BSZ*DH)

typedef unsigned long long u64;

// ---------------------------------------------------------------------------
// scratch (__device__ globals; no runtime allocation allowed)
// ---------------------------------------------------------------------------
__device__ float g_qproj[BSZ * HD];                 // q_proj + ba
__device__ float g_part[8 * BD];                    // logit partial slices
__device__ __nv_bfloat16 g_hh_hi[(size_t)BD * HD];  // h_history split high
__device__ __nv_bfloat16 g_hh_lo[(size_t)BD * HD];  // h_history split low
__device__ __nv_bfloat16 g_w_hi[HD * HD];           // Wah split high
__device__ __nv_bfloat16 g_w_lo[HD * HD];           // Wah split low

// ---------------------------------------------------------------------------
// helpers
// ---------------------------------------------------------------------------
__device__ __forceinline__ uint32_t smem_u32(const void* p) {
    uint32_t a;
    asm("{ .reg .u64 t; cvta.to.shared.u64 t, %1; cvt.u32.u64 %0, t; }"
        : "=r"(a) : "l"(p));
    return a;
}
__device__ __forceinline__ void cpa16(uint32_t dst, const void* src) {
    asm volatile("cp.async.cg.shared.global [%0], [%1], 16;" :: "r"(dst), "l"(src));
}
__device__ __forceinline__ void ldsm4(uint32_t* r, uint32_t addr) {
    asm volatile("ldmatrix.sync.aligned.m8n8.x4.shared.b16 {%0,%1,%2,%3}, [%4];"
        : "=r"(r[0]), "=r"(r[1]), "=r"(r[2]), "=r"(r[3]) : "r"(addr));
}
__device__ __forceinline__ void mma16816(float* c, const uint32_t* a, const uint32_t* b) {
    asm volatile(
        "mma.sync.aligned.m16n8k16.row.col.f32.bf16.bf16.f32 "
        "{%0,%1,%2,%3}, {%4,%5,%6,%7}, {%8,%9}, {%0,%1,%2,%3};"
        : "+f"(c[0]), "+f"(c[1]), "+f"(c[2]), "+f"(c[3])
        : "r"(a[0]), "r"(a[1]), "r"(a[2]), "r"(a[3]), "r"(b[0]), "r"(b[1]));
}
__device__ __forceinline__ float fast_tanh(float x) {
    float e = __expf(2.0f * x);
    return 1.0f - 2.0f / (e + 1.0f);
}

// ---------------------------------------------------------------------------
// convert_hh: h_history fp32 -> bf16 hi/lo (one pass; keeps score loop lean)
// ---------------------------------------------------------------------------
__global__ __launch_bounds__(256) void convert_hh_kernel(const float* __restrict__ x) {
    int i = blockIdx.x * blockDim.x + threadIdx.x;
    float4 v = reinterpret_cast<const float4*>(x)[i];
    __nv_bfloat162 h01 = __floats2bfloat162_rn(v.x, v.y);
    __nv_bfloat162 h23 = __floats2bfloat162_rn(v.z, v.w);
    __nv_bfloat162 l01 = __floats2bfloat162_rn(
        v.x - __bfloat162float(h01.x), v.y - __bfloat162float(h01.y));
    __nv_bfloat162 l23 = __floats2bfloat162_rn(
        v.z - __bfloat162float(h23.x), v.w - __bfloat162float(h23.y));
    reinterpret_cast<__nv_bfloat162*>(g_hh_hi)[2 * i]     = h01;
    reinterpret_cast<__nv_bfloat162*>(g_hh_hi)[2 * i + 1] = h23;
    reinterpret_cast<__nv_bfloat162*>(g_hh_lo)[2 * i]     = l01;
    reinterpret_cast<__nv_bfloat162*>(g_hh_lo)[2 * i + 1] = l23;
}

// ---------------------------------------------------------------------------
// convert_w: Wah fp32 -> bf16 hi/lo (1 MB, trivial)
// ---------------------------------------------------------------------------
__global__ __launch_bounds__(256) void convert_w_kernel(const float* __restrict__ x) {
    int i = blockIdx.x * blockDim.x + threadIdx.x;
    float4 v = reinterpret_cast<const float4*>(x)[i];
    __nv_bfloat162 h01 = __floats2bfloat162_rn(v.x, v.y);
    __nv_bfloat162 h23 = __floats2bfloat162_rn(v.z, v.w);
    __nv_bfloat162 l01 = __floats2bfloat162_rn(
        v.x - __bfloat162float(h01.x), v.y - __bfloat162float(h01.y));
    __nv_bfloat162 l23 = __floats2bfloat162_rn(
        v.z - __bfloat162float(h23.x), v.w - __bfloat162float(h23.y));
    reinterpret_cast<__nv_bfloat162*>(g_w_hi)[2 * i]     = h01;
    reinterpret_cast<__nv_bfloat162*>(g_w_hi)[2 * i + 1] = h23;
    reinterpret_cast<__nv_bfloat162*>(g_w_lo)[2 * i]     = l01;
    reinterpret_cast<__nv_bfloat162*>(g_w_lo)[2 * i + 1] = l23;
}

// ---------------------------------------------------------------------------
// qproj: M=1024 N=512 K=1024 fp32; 32x64 tiles -> 256 CTAs
// ---------------------------------------------------------------------------
#define QBK 32
__global__ __launch_bounds__(128) void qproj_kernel(
    const float* __restrict__ h_tilde, const float* __restrict__ c_t,
    const float* __restrict__ Waq, const float* __restrict__ ba)
{
    __shared__ float As[QBK][36];
    __shared__ float Bs[QBK][68];
    const int t  = threadIdx.x;
    const int tx = t & 15, ty = t >> 4;
    const int b0 = blockIdx.x * 32;
    const int g0 = blockIdx.y * 64;

    float acc[4][4] = {};

    for (int k0 = 0; k0 < 2 * HD; k0 += QBK) {
#pragma unroll
        for (int i = 0; i < 8; i++) {
            int idx = t + i * 128;
            int r = idx >> 5, c = idx & 31;
            int j = k0 + c;
            As[c][r] = (j < HD) ? h_tilde[(b0 + r) * HD + j]
                                : c_t[(b0 + r) * HD + (j - HD)];
        }
#pragma unroll
        for (int i = 0; i < 16; i++) {
            int idx = t + i * 128;
            int r = idx >> 5, c = idx & 31;
            Bs[c][r] = Waq[(g0 + r) * (2 * HD) + k0 + c];
        }
        __syncthreads();
#pragma unroll
        for (int k = 0; k < QBK; k++) {
            float4 av = *reinterpret_cast<const float4*>(&As[k][ty * 4]);
            float4 bv = *reinterpret_cast<const float4*>(&Bs[k][tx * 4]);
            float a[4] = {av.x, av.y, av.z, av.w};
            float bb[4] = {bv.x, bv.y, bv.z, bv.w};
#pragma unroll
            for (int i = 0; i < 4; i++)
#pragma unroll
                for (int jj = 0; jj < 4; jj++)
                    acc[i][jj] = fmaf(a[i], bb[jj], acc[i][jj]);
        }
        __syncthreads();
    }

#pragma unroll
    for (int i = 0; i < 4; i++)
#pragma unroll
        for (int jj = 0; jj < 4; jj++)
            g_qproj[(b0 + ty * 4 + i) * HD + (g0 + tx * 4 + jj)] =
                acc[i][jj] + ba[g0 + tx * 4 + jj];
}

// ---------------------------------------------------------------------------
// score: HMMA GEMM, pre-split bf16 operands via cp.async.
// CTA tile 128(M) x 128(N), 8 warps (4M x 2N), warp tile 32x64, 2 CTAs/SM.
// R12 change: compute() is software-pipelined at p-granularity — B frags are
// loaded per 16-col slice and immediately consumed by 12 MMAs, so LDSM
// streams under HMMA instead of alternating whole phases (regs stay <=128).
// ---------------------------------------------------------------------------
#define SSTR    40                 // smem row stride in halves (80 B)
#define TILE_H  (128 * SSTR)       // halves per 128x32 tile
#define STAGE_H (4 * TILE_H)       // Ah, Al, Bh, Bl
#define OFF_AL  TILE_H
#define OFF_BH  (2 * TILE_H)
#define OFF_BL  (3 * TILE_H)
#define NCHUNK  16                 // 512/32

__global__ __launch_bounds__(256, 2) void score_mma_kernel(const float* __restrict__ v_t)
{
    extern __shared__ __nv_bfloat16 sm[];
    __shared__ float v_sh[128], qp_sh[128];

    const int t = threadIdx.x;
    const int l = t & 31, wid = t >> 5;
    const int warp_m = wid & 3;       // M offset 32*warp_m
    const int warp_n = wid >> 2;      // N offset 64*warp_n
    const int c2 = (l & 3) * 2;

    const int g0 = blockIdx.x * 128;  // fast dim -> A-tile L2 reuse (4 CTAs)
    const int m0 = blockIdx.y * 128;
    const int b  = m0 / DH;

    const __nv_bfloat16* srcAh = g_hh_hi + (size_t)m0 * HD;
    const __nv_bfloat16* srcAl = g_hh_lo + (size_t)m0 * HD;
    const __nv_bfloat16* srcBh = g_w_hi + (size_t)g0 * HD;
    const __nv_bfloat16* srcBl = g_w_lo + (size_t)g0 * HD;

    const uint32_t smem_base = smem_u32(sm);

    // stage loader: 4 tiles (Ah,Al,Bh,Bl), each 128 rows x 32 halves.
    // 512 segs/tile; 2 tasks/thread; 4 cpa16 per task (one per tile).
    auto cpStage = [&](int ch, int st) {
        const uint32_t base = smem_base + (uint32_t)st * STAGE_H * 2;
        const int k0 = ch * 32;
#pragma unroll
        for (int j = 0; j < 2; j++) {
            int task = t + j * 256;               // 0..511
            int row = task >> 2, seg = task & 3;  // row 0..127, seg 0..3
            uint32_t off = (uint32_t)(row * SSTR) * 2 + (uint32_t)seg * 16;
            size_t so = (size_t)row * HD + k0 + seg * 8;
            cpa16(base + off,              srcAh + so);
            cpa16(base + OFF_AL * 2 + off, srcAl + so);
            cpa16(base + OFF_BH * 2 + off, srcBh + so);
            cpa16(base + OFF_BL * 2 + off, srcBl + so);
        }
        asm volatile("cp.async.commit_group;" ::: "memory");
    };

    float acc[2][8][4];
#pragma unroll
    for (int mt = 0; mt < 2; mt++)
#pragma unroll
        for (int nt = 0; nt < 8; nt++)
#pragma unroll
            for (int e = 0; e < 4; e++) acc[mt][nt][e] = 0.0f;

    auto compute = [&](int st) {
        const uint32_t sb = smem_base + (uint32_t)st * STAGE_H * 2;
#pragma unroll
        for (int ks = 0; ks < 2; ks++) {
            const int kb = ks * 16;
            // A frags for this ks (hi+lo): 4 ldsm4, 32 regs, live all ks
            uint32_t a_hi[2][4], a_lo[2][4];
#pragma unroll
            for (int mt = 0; mt < 2; mt++) {
                int row = warp_m * 32 + mt * 16 + (l & 7) + ((l >> 3) & 1) * 8;
                int col = kb + ((l >> 4) & 1) * 8;
                uint32_t off = (uint32_t)(row * SSTR + col) * 2;
                ldsm4(a_hi[mt], sb + off);
                ldsm4(a_lo[mt], sb + OFF_AL * 2 + off);
            }
            // B frags streamed per p; 12 MMAs consume each pair immediately,
            // covering the next p's LDSM latency and crossbar time.
#pragma unroll
            for (int p = 0; p < 4; p++) {
                uint32_t bh[4], bl[4];
                int n = warp_n * 64 + p * 16 + (l & 7) + ((l >> 4) & 1) * 8;
                int col = kb + ((l >> 3) & 1) * 8;
                uint32_t off = (uint32_t)(n * SSTR + col) * 2;
                ldsm4(bh, sb + OFF_BH * 2 + off);
                ldsm4(bl, sb + OFF_BL * 2 + off);
#pragma unroll
                for (int h = 0; h < 2; h++)
#pragma unroll
                    for (int mt = 0; mt < 2; mt++)
                        mma16816(acc[mt][2 * p + h], a_hi[mt], &bh[2 * h]);
#pragma unroll
                for (int h = 0; h < 2; h++)
#pragma unroll
                    for (int mt = 0; mt < 2; mt++)
                        mma16816(acc[mt][2 * p + h], a_hi[mt], &bl[2 * h]);
#pragma unroll
                for (int h = 0; h < 2; h++)
#pragma unroll
                    for (int mt = 0; mt < 2; mt++)
                        mma16816(acc[mt][2 * p + h], a_lo[mt], &bh[2 * h]);
            }
        }
    };

    cpStage(0, 0);

    if (t < 128) {
        v_sh[t]  = v_t[g0 + t];
        qp_sh[t] = g_qproj[b * HD + g0 + t];
    }

#pragma unroll 1
    for (int i = 0; i < NCHUNK; i++) {
        const int s = i & 1;
        if (i + 1 < NCHUNK) {
            cpStage(i + 1, s ^ 1);   // issue early: loads lead by one compute
            asm volatile("cp.async.wait_group 1;" ::: "memory"); // chunk i done
        } else {
            asm volatile("cp.async.wait_group 0;" ::: "memory");
        }
        __syncthreads();             // stage s data visible to all warps
        compute(s);
        __syncthreads();             // protect stage s from next cp overwrite
    }

    // epilogue: tanh + v-dot, quad reduce, store into partial slice
    const int slice = blockIdx.x * 2 + warp_n;     // 0..7
    const int q = l >> 2;
#pragma unroll
    for (int mt = 0; mt < 2; mt++) {
        float rs0 = 0.0f, rs1 = 0.0f;
#pragma unroll
        for (int nt = 0; nt < 8; nt++) {
            const int gbase = warp_n * 64 + nt * 8 + c2;
            const float vq0 = v_sh[gbase],     qq0 = qp_sh[gbase];
            const float vq1 = v_sh[gbase + 1], qq1 = qp_sh[gbase + 1];
            rs0 += vq0 * fast_tanh(acc[mt][nt][0] + qq0);
            rs0 += vq1 * fast_tanh(acc[mt][nt][1] + qq1);
            rs1 += vq0 * fast_tanh(acc[mt][nt][2] + qq0);
            rs1 += vq1 * fast_tanh(acc[mt][nt][3] + qq1);
        }
        rs0 += __shfl_xor_sync(0xffffffffu, rs0, 1);
        rs0 += __shfl_xor_sync(0xffffffffu, rs0, 2);
        rs1 += __shfl_xor_sync(0xffffffffu, rs1, 1);
        rs1 += __shfl_xor_sync(0xffffffffu, rs1, 2);
        if ((l & 3) == 0) {
            const int rowb = m0 + warp_m * 32 + mt * 16 + q;
            g_part[(size_t)slice * BD + rowb]     = rs0;
            g_part[(size_t)slice * BD + rowb + 8] = rs1;
        }
    }
}

// ---------------------------------------------------------------------------
// softmax: sum 8 partial slices, then softmax over d
// ---------------------------------------------------------------------------
__global__ __launch_bounds__(DH) void softmax_kernel(float* __restrict__ alpha_out)
{
    __shared__ float red[DH];
    const int b = blockIdx.x, d = threadIdx.x;
    const int row = b * DH + d;
    float x = 0.0f;
#pragma unroll
    for (int s = 0; s < 8; s++) x += g_part[(size_t)s * BD + row];
    red[d] = x;
    __syncthreads();
    for (int s = DH / 2; s > 0; s >>= 1) {
        if (d < s) red[d] = fmaxf(red[d], red[d + s]);
        __syncthreads();
    }
    float mx = red[0];
    __syncthreads();
    float e = __expf(x - mx);
    red[d] = e;
    __syncthreads();
    for (int s = DH / 2; s > 0; s >>= 1) {
        if (d < s) red[d] += red[d + s];
        __syncthreads();
    }
    alpha_out[row] = e / red[0];
}

// ---------------------------------------------------------------------------
// e_t = alpha . h_history  — 128 thr x float4, full-row coalesced
// ---------------------------------------------------------------------------
__global__ __launch_bounds__(128) void et_kernel(
    const float* __restrict__ hh, const float* __restrict__ alpha,
    float* __restrict__ e_out)
{
    __shared__ float al[DH];
    const int b = blockIdx.x, t = threadIdx.x;
    al[t]       = alpha[b * DH + t];
    al[t + 128] = alpha[b * DH + t + 128];
    __syncthreads();
    const float4* basep = reinterpret_cast<const float4*>(
        hh + (size_t)b * DH * HD) + t;
    float ax = 0.f, ay = 0.f, az = 0.f, aw = 0.f;
#pragma unroll 4
    for (int d = 0; d < DH; d++) {
        float4 v = basep[(size_t)d * (HD / 4)];
        float a = al[d];
        ax = fmaf(a, v.x, ax);
        ay = fmaf(a, v.y, ay);
        az = fmaf(a, v.z, az);
        aw = fmaf(a, v.w, aw);
    }
    reinterpret_cast<float4*>(e_out + b * HD)[t] = make_float4(ax, ay, az, aw);
}

// ---------------------------------------------------------------------------
// launch
// inputs: 0 h_tilde | 1 c_t | 2 h_history | 3 Waq | 4 Wah | 5 ba | 6 v_t
// out = [e_t (B*H) | alpha (B*D)]
// ---------------------------------------------------------------------------
extern "C" void kernel_launch(void* const* d_in, const int* in_sizes, int n_in,
                              void* d_out, int out_size)
{
    const float* h_tilde = (const float*)d_in[0];
    const float* c_t     = (const float*)d_in[1];
    const float* hh      = (const float*)d_in[2];
    const float* Waq     = (const float*)d_in[3];
    const float* Wah     = (const float*)d_in[4];
    const float* ba      = (const float*)d_in[5];
    const float* v_t     = (const float*)d_in[6];

    float* out       = (float*)d_out;
    float* e_out     = out;               // [B, H]
    float* alpha_out = out + BSZ * HD;    // [B, D]

    cudaFuncSetAttribute(score_mma_kernel,
                         cudaFuncAttributeMaxDynamicSharedMemorySize,
                         2 * STAGE_H * 2);

    convert_w_kernel<<<(HD * HD / 4) / 256, 256>>>(Wah);            // 1
    convert_hh_kernel<<<((size_t)BD * HD / 4) / 256, 256>>>(hh);    // 2

    dim3 g1(BSZ / 32, HD / 64);
    qproj_kernel<<<g1, 128>>>(h_tilde, c_t, Waq, ba);               // 3

    dim3 g2(HD / 128, BD / 128);   // g0 fastest -> A-tile L2 reuse (4 CTAs)
    score_mma_kernel<<<g2, 256, 2 * STAGE_H * 2>>>(v_t);            // 4 (profiled)

    softmax_kernel<<<BSZ, DH>>>(alpha_out);                         // 5

    et_kernel<<<BSZ, 128>>>(hh, alpha_out, e_out);                  // 6
}